// round 16
// baseline (speedup 1.0000x reference)
#include <cuda_runtime.h>
#include <cuda_bf16.h>

// HierarchicalSoftmax fused kernel, round 15.
// Base = round-14 winner (cp.async-staged deep rows, aliased deep partial
// slots, shallow load-use overlap). Delta: __launch_bounds__(128,10) -> ptxas
// targets <=51 regs so 10 blocks (40 warps) fit per SM instead of 9; shared
// scratch for the final reduction reuses one buffer to stay under the smem
// ceiling at 10 blocks.
//
// Inputs (metadata order):
//   d_in[0]: embeddings float32 [B, E]   (B=16384, E=128)
//   d_in[1]: word_idx   int32   [B]
//   d_in[2]: W          float32 [V-1, E] (V=131072)
//   d_in[3]: b          float32 [V-1]
// Output: float32 scalar = mean over B of sum over 17 path nodes of BCE.

#define HS_D   17
#define TPB    128
#define WPB    4
#define MAX_BLOCKS 8192
#define NDEEP  8            // depths 0..7: DRAM-tier rows, cp.async-staged
#define NSHAL  (HS_D - NDEEP)   // 9 shallow (cache-hot) rows
#define ROWB   512          // bytes per W row
#define DSLOT  528          // byte offset of deep slot j inside sdeep (528*j)
#define SSTRIDE 36          // words per shallow slot (32 + 4 pad)

typedef unsigned long long u64;

__device__ float        g_hs_partials[MAX_BLOCKS];
__device__ unsigned int g_hs_count = 0;   // self-resetting ticket

__device__ __forceinline__ u64 ffma2(u64 a, u64 b, u64 c)
{
    u64 d;
    asm("fma.rn.f32x2 %0, %1, %2, %3;" : "=l"(d) : "l"(a), "l"(b), "l"(c));
    return d;
}

// per-lane partial of a row: 4 floats (2 packed f32x2) dotted with embedding
__device__ __forceinline__ float dot4(const ulonglong2 w, const ulonglong2 e)
{
    u64 p = ffma2(w.y, e.y, ffma2(w.x, e.x, 0ull));
    float lo, hi;
    asm("mov.b64 {%0,%1}, %2;" : "=f"(lo), "=f"(hi) : "l"(p));
    return lo + hi;
}

// sum a 32-float partial slot: 8 float4 reads (conflict-free), pairwise tree
__device__ __forceinline__ float sum_slot(const float* base)
{
    const float4* pv = reinterpret_cast<const float4*>(base);
    const float4 a0 = pv[0], a1 = pv[1], a2 = pv[2], a3 = pv[3];
    const float4 a4 = pv[4], a5 = pv[5], a6 = pv[6], a7 = pv[7];
    return (((a0.x + a0.y) + (a0.z + a0.w))
         +  ((a1.x + a1.y) + (a1.z + a1.w)))
         + (((a2.x + a2.y) + (a2.z + a2.w))
         +  ((a3.x + a3.y) + (a3.z + a3.w)))
         + (((a4.x + a4.y) + (a4.z + a4.w))
         +  ((a5.x + a5.y) + (a5.z + a5.w)))
         + (((a6.x + a6.y) + (a6.z + a6.w))
         +  ((a7.x + a7.y) + (a7.z + a7.w)));
}

__global__ __launch_bounds__(TPB, 10)
void hs_fused_kernel(const float*  __restrict__ emb,
                     const int*    __restrict__ word_idx,
                     const float4* __restrict__ W4,
                     const float*  __restrict__ bias,
                     float*        __restrict__ out,
                     int B, int Vm1, float invB)
{
    const int warp  = blockIdx.x * WPB + (threadIdx.x >> 5);
    const int wslot = threadIdx.x >> 5;
    const int lane  = threadIdx.x & 31;

    // Deep staging (8 x 512B/warp); deep partial slot j aliased at byte 528*j
    // (written only after row j is consumed). Shallow slots separate.
    __shared__ __align__(16) char  sdeep[WPB][NDEEP * ROWB];
    __shared__ __align__(16) float sshal[WPB][NSHAL * SSTRIDE];
    __shared__ __align__(16) float sred[TPB];   // reused: warp sums + final reduce
    __shared__ bool is_last;

    float warp_sum = 0.0f;

    if (warp < B) {
        const char* __restrict__ Wb = reinterpret_cast<const char*>(W4);

        // 1-based leaf heap index: W-node at depth d = (leaf1 >> (d+1)) - 1;
        // direction bit at depth d = ((leaf1 >> d) & 1) ^ 1.
        const unsigned leaf1 = (unsigned)__ldg(&word_idx[warp])
                             + (unsigned)(Vm1 + 1);

        const int laneoff = lane * 16 - 512;   // row n starts at ((n+1)<<9)-512

        // ---- stage the 8 deep rows to smem with cp.async (no reg cost) ----
        const unsigned sd_base = (unsigned)__cvta_generic_to_shared(
                                     &sdeep[wslot][0]);
        #pragma unroll
        for (int j = 0; j < NDEEP; ++j) {
            const char* gsrc = Wb + (((size_t)(leaf1 >> (j + 1)) << 9) + laneoff);
            asm volatile("cp.async.cg.shared.global [%0], [%1], 16;"
                         :: "r"(sd_base + j * ROWB + lane * 16), "l"(gsrc)
                         : "memory");
        }
        asm volatile("cp.async.commit_group;" ::: "memory");

        // Lane owns embedding floats [4*lane, 4*lane+4): one 16B load.
        const ulonglong2 e = __ldg(reinterpret_cast<const ulonglong2*>(
            reinterpret_cast<const char*>(emb) + ((size_t)warp << 9) + lane * 16));

        // Epilogue metadata + bias prefetch (overlaps the async batch).
        const int   d  = (lane < HS_D) ? lane : (HS_D - 1);
        const int   nd = (int)((leaf1 >> (d + 1)) - 1u);
        const float bd = __ldg(&bias[nd]);

        // ---- shallow rows (depths 8..16, cache-hot): load-use overlap ----
        #pragma unroll
        for (int j = NDEEP; j < HS_D; ++j) {
            const size_t off = ((size_t)(leaf1 >> (j + 1)) << 9) + laneoff;
            const ulonglong2 ws =
                __ldg(reinterpret_cast<const ulonglong2*>(Wb + off));
            sshal[wslot][(j - NDEEP) * SSTRIDE + lane] = dot4(ws, e);
        }

        // ---- wait for the deep batch, consume + write aliased slots ----
        asm volatile("cp.async.wait_group 0;" ::: "memory");
        #pragma unroll
        for (int j = 0; j < NDEEP; ++j) {
            const ulonglong2 wdj = *reinterpret_cast<const ulonglong2*>(
                &sdeep[wslot][j * ROWB + lane * 16]);
            const float pj = dot4(wdj, e);
            *reinterpret_cast<float*>(
                &sdeep[wslot][j * DSLOT + lane * 4]) = pj;
        }
        __syncwarp();

        // ---- transposed epilogue: lane d sums node d's 32 partials ----
        const float* slot_base = (d < NDEEP)
            ? reinterpret_cast<const float*>(&sdeep[wslot][d * DSLOT])
            : &sshal[wslot][(d - NDEEP) * SSTRIDE];
        const float dot = sum_slot(slot_base);

        const float s = dot + bd;
        const float t = (float)(((leaf1 >> d) & 1u) ^ 1u);
        float bce = fmaxf(s, 0.0f) - s * t + __logf(1.0f + __expf(-fabsf(s)));
        if (lane >= HS_D) bce = 0.0f;

        // One butterfly for the whole sample.
        bce += __shfl_xor_sync(0xffffffffu, bce, 16);
        bce += __shfl_xor_sync(0xffffffffu, bce, 8);
        bce += __shfl_xor_sync(0xffffffffu, bce, 4);
        bce += __shfl_xor_sync(0xffffffffu, bce, 2);
        bce += __shfl_xor_sync(0xffffffffu, bce, 1);
        warp_sum = bce;
    }

    // ---- block reduction + last-block grid reduction (deterministic) ----
    if (lane == 0) sred[wslot] = warp_sum;
    __syncthreads();
    if (threadIdx.x == 0) {
        float ssum = 0.0f;
        #pragma unroll
        for (int i = 0; i < WPB; ++i) ssum += sred[i];
        g_hs_partials[blockIdx.x] = ssum;
        __threadfence();
        unsigned tk = atomicInc(&g_hs_count, gridDim.x - 1);
        is_last = (tk == gridDim.x - 1);
    }
    __syncthreads();

    if (is_last) {
        float a = 0.0f;
        for (int i = threadIdx.x; i < (int)gridDim.x; i += TPB)
            a += g_hs_partials[i];
        __syncthreads();           // sred[0..WPB) reads above are done
        sred[threadIdx.x] = a;
        __syncthreads();
        #pragma unroll
        for (int ofs = TPB / 2; ofs > 0; ofs >>= 1) {
            if (threadIdx.x < ofs) sred[threadIdx.x] += sred[threadIdx.x + ofs];
            __syncthreads();
        }
        if (threadIdx.x == 0) out[0] = sred[0] * invB;
    }
}

extern "C" void kernel_launch(void* const* d_in, const int* in_sizes, int n_in,
                              void* d_out, int out_size)
{
    const float*  emb      = (const float*) d_in[0];
    const int*    word_idx = (const int*)   d_in[1];
    const float4* W4       = (const float4*)d_in[2];
    const float*  bias     = (const float*) d_in[3];
    float* out = (float*)d_out;

    const int B   = in_sizes[1];   // 16384
    const int Vm1 = in_sizes[3];   // V-1 = 131071

    int nblocks = (B + WPB - 1) / WPB;            // 4096
    if (nblocks > MAX_BLOCKS) nblocks = MAX_BLOCKS;

    hs_fused_kernel<<<nblocks, TPB>>>(emb, word_idx, W4, bias, out,
                                      B, Vm1, 1.0f / (float)B);
}